// round 14
// baseline (speedup 1.0000x reference)
#include <cuda_runtime.h>
#include <cuda_bf16.h>
#include <cstdint>

#define NNODES 50000
#define NEDGES 600000
#define NFEAT  128
#define F2     256
#define CF     384
#define HID    512
#define NOUT   128
#define NGR    128
#define NBLK   49          // ceil(50000/1024)
#define NB     64          // blocks in fused CSR kernel (co-resident)

__device__ __forceinline__ float f2tf32(float x) {
    float y;
    asm("cvt.rna.tf32.f32 %0, %1;" : "=f"(y) : "f"(x));
    return y;
}

__device__ __forceinline__ void mma_tf32(float c[4], const uint32_t a[4], const uint32_t b[2]) {
    asm volatile(
        "mma.sync.aligned.m16n8k8.row.col.f32.tf32.tf32.f32 "
        "{%0,%1,%2,%3}, {%4,%5,%6,%7}, {%8,%9}, {%0,%1,%2,%3};"
        : "+f"(c[0]), "+f"(c[1]), "+f"(c[2]), "+f"(c[3])
        : "r"(a[0]), "r"(a[1]), "r"(a[2]), "r"(a[3]), "r"(b[0]), "r"(b[1]));
}

__device__ __forceinline__ uint32_t smem_u32(const void* p) {
    uint32_t a;
    asm("{ .reg .u64 t; cvta.to.shared.u64 t, %1; cvt.u32.u64 %0, t; }" : "=r"(a) : "l"(p));
    return a;
}

__device__ __forceinline__ void cp16(uint32_t dst, const void* src, int sz) {
    asm volatile("cp.async.ca.shared.global [%0], [%1], 16, %2;"
                 :: "r"(dst), "l"(src), "r"(sz) : "memory");
}
#define CP_COMMIT() asm volatile("cp.async.commit_group;" ::: "memory")
#define CP_WAIT(N)  asm volatile("cp.async.wait_group %0;" :: "n"(N) : "memory")

// ---------------- scratch ----------------
__device__ __align__(256) int   g_scnt[NNODES];
__device__ __align__(256) float g_dinv[NNODES];
__device__ __align__(256) int   g_cnt[NNODES];
__device__ __align__(256) int   g_rowptr[NNODES + 1];
__device__ __align__(256) int   g_cursor[NNODES];
__device__ __align__(256) int   g_bsum[NBLK];
__device__ __align__(256) int   g_csr_src[NEDGES];
__device__ __align__(256) float g_csr_w[NEDGES];
__device__ __align__(256) float g_Tx1[(size_t)NNODES * NFEAT];
__device__ __align__(256) float g_Tx2[(size_t)NNODES * NFEAT];
__device__ __align__(256) float g_gx1[(size_t)NNODES * NFEAT];
__device__ __align__(256) float g_gx2[(size_t)NNODES * F2];
__device__ __align__(256) float g_Wt1[NFEAT * CF];
__device__ __align__(256) float g_Wt2[F2 * CF];
__device__ int g_is64;

// grid barrier state (fused CSR kernel)
__device__ int g_bar_count;
__device__ volatile int g_bar_sense;

__device__ __forceinline__ void grid_barrier(int target) {
    __syncthreads();
    if (threadIdx.x == 0) {
        __threadfence();
        if (atomicAdd(&g_bar_count, 1) == NB - 1) {
            atomicExch(&g_bar_count, 0);
            __threadfence();
            g_bar_sense = target;
        } else {
            while (g_bar_sense < target) {}
        }
        __threadfence();
    }
    __syncthreads();
}

template <int ID>
__device__ __forceinline__ float* bufptr(const float* ext) {
    if (ID == 1) return g_Tx1;
    if (ID == 2) return g_Tx2;
    if (ID == 3) return g_gx1;
    if (ID == 4) return g_gx2;
    return (float*)ext;
}

__device__ __forceinline__ int load_idx(const void* p, long long i, int is64) {
    if (is64) return (int)((const long long*)p)[i];
    return ((const int*)p)[i];
}

// ---------------- fused CSR build ----------------
__global__ void __launch_bounds__(1024) csr_kernel(const void* __restrict__ ei,
                                                   const float* __restrict__ W1,
                                                   const float* __restrict__ W2) {
    __shared__ int warpsum[32];
    __shared__ int sb[64];
    int tid = threadIdx.x;
    int b = blockIdx.x;
    int gt = b * 1024 + tid;
    int wid = tid >> 5, lane = tid & 31;
    int base = g_bar_sense;

    // ---- P0: zero counters, dtype detect, weight transpose ----
    if (gt < NNODES) { g_scnt[gt] = 0; g_cnt[gt] = 0; }
    if (gt == 0) {
        const int* p = (const int*)ei;
        int orv = 0;
        for (int j = 0; j < 64; j++) orv |= p[2 * j + 1];
        g_is64 = (orv == 0) ? 1 : 0;
    }
    for (int i = gt; i < CF * NFEAT; i += NB * 1024) {
        int kk = i / NFEAT, n = i % NFEAT;
        g_Wt1[(size_t)n * CF + kk] = f2tf32(W1[i]);
    }
    for (int i = gt; i < CF * F2; i += NB * 1024) {
        int kk = i / F2, n = i % F2;
        g_Wt2[(size_t)n * CF + kk] = f2tf32(W2[i]);
    }
    grid_barrier(base + 1);

    // ---- P1: degree counts ----
    int is64 = __ldcg(&g_is64);
    for (int e = gt; e < NEDGES; e += NB * 1024) {
        int s = load_idx(ei, e, is64);
        int d = load_idx(ei, (long long)NEDGES + e, is64);
        if (s < 0 || s >= NNODES || d < 0 || d >= NNODES) continue;
        atomicAdd(&g_scnt[s], 1);
        atomicAdd(&g_cnt[d], 1);
    }
    grid_barrier(base + 2);

    // ---- P2: dinv + per-chunk exclusive scan ----
    if (gt < NNODES) {
        float dg = (float)__ldcg(&g_scnt[gt]);
        g_dinv[gt] = (dg > 0.f) ? rsqrtf(dg) : 0.f;
    }
    {
        int v = (b < NBLK && gt < NNODES) ? __ldcg(&g_cnt[gt]) : 0;
        int x = v;
#pragma unroll
        for (int off = 1; off < 32; off <<= 1) {
            int n = __shfl_up_sync(0xFFFFFFFFu, x, off);
            if (lane >= off) x += n;
        }
        if (lane == 31) warpsum[wid] = x;
        __syncthreads();
        if (wid == 0) {
            int y = warpsum[lane];
#pragma unroll
            for (int off = 1; off < 32; off <<= 1) {
                int n = __shfl_up_sync(0xFFFFFFFFu, y, off);
                if (lane >= off) y += n;
            }
            warpsum[lane] = y;
        }
        __syncthreads();
        int incl = x + (wid > 0 ? warpsum[wid - 1] : 0);
        if (b < NBLK) {
            if (gt < NNODES) g_rowptr[gt] = incl - v;
            if (tid == 1023) g_bsum[b] = incl;
        }
    }
    grid_barrier(base + 3);

    // ---- P3: block-sum scan + finalize rowptr/cursor ----
    if (tid < 64) sb[tid] = (tid < NBLK) ? __ldcg(&g_bsum[tid]) : 0;
    __syncthreads();
#pragma unroll
    for (int off = 1; off < 64; off <<= 1) {
        int t = (tid < 64 && tid >= off) ? sb[tid - off] : 0;
        __syncthreads();
        if (tid < 64) sb[tid] += t;
        __syncthreads();
    }
    if (b == 0 && tid == 0) g_rowptr[NNODES] = sb[NBLK - 1];
    if (gt < NNODES) {
        int s_off = (b > 0) ? sb[b - 1] : 0;
        int o = g_rowptr[gt] + s_off;
        g_rowptr[gt] = o;
        g_cursor[gt] = o;
    }
    grid_barrier(base + 4);

    // ---- P4: scatter edges into CSR ----
    for (int e = gt; e < NEDGES; e += NB * 1024) {
        int s = load_idx(ei, e, is64);
        int d = load_idx(ei, (long long)NEDGES + e, is64);
        if (s < 0 || s >= NNODES || d < 0 || d >= NNODES) continue;
        float w = -__ldcg(&g_dinv[s]) * __ldcg(&g_dinv[d]);
        int pos = atomicAdd(&g_cursor[d], 1);
        g_csr_src[pos] = s;
        g_csr_w[pos]   = w;
    }
}

// ---------------- sparse propagation (outputs tf32-rounded; unroll x4) ----------------
template <int XID, int PID, int OID>
__global__ void prop_kernel(const float* __restrict__ ext, float alpha) {
    const float* x = bufptr<XID>(ext);
    float* out = bufptr<OID>(ext);
    int warp = (blockIdx.x * blockDim.x + threadIdx.x) >> 5;
    if (warp >= NNODES) return;
    int lane = threadIdx.x & 31;
    int beg = g_rowptr[warp];
    int end = g_rowptr[warp + 1];
    float4 acc = make_float4(0.f, 0.f, 0.f, 0.f);
    int j = beg;
    for (; j + 4 <= end; j += 4) {
        int s0 = g_csr_src[j],     s1 = g_csr_src[j + 1];
        int s2 = g_csr_src[j + 2], s3 = g_csr_src[j + 3];
        float w0 = g_csr_w[j],     w1 = g_csr_w[j + 1];
        float w2 = g_csr_w[j + 2], w3 = g_csr_w[j + 3];
        const float4 v0 = *(const float4*)(x + (size_t)s0 * NFEAT + lane * 4);
        const float4 v1 = *(const float4*)(x + (size_t)s1 * NFEAT + lane * 4);
        const float4 v2 = *(const float4*)(x + (size_t)s2 * NFEAT + lane * 4);
        const float4 v3 = *(const float4*)(x + (size_t)s3 * NFEAT + lane * 4);
        acc.x += w0 * v0.x + w1 * v1.x + w2 * v2.x + w3 * v3.x;
        acc.y += w0 * v0.y + w1 * v1.y + w2 * v2.y + w3 * v3.y;
        acc.z += w0 * v0.z + w1 * v1.z + w2 * v2.z + w3 * v3.z;
        acc.w += w0 * v0.w + w1 * v1.w + w2 * v2.w + w3 * v3.w;
    }
    for (; j < end; j++) {
        int s   = g_csr_src[j];
        float w = g_csr_w[j];
        const float4 v = *(const float4*)(x + (size_t)s * NFEAT + lane * 4);
        acc.x += w * v.x; acc.y += w * v.y; acc.z += w * v.z; acc.w += w * v.w;
    }
    size_t o = (size_t)warp * NFEAT + lane * 4;
    if (PID >= 0) {
        const float* xprev = bufptr<(PID >= 0 ? PID : 0)>(ext);
        const float4 p = *(const float4*)(xprev + o);
        acc.x = alpha * acc.x - p.x;
        acc.y = alpha * acc.y - p.y;
        acc.z = alpha * acc.z - p.z;
        acc.w = alpha * acc.w - p.w;
    }
    acc.x = f2tf32(acc.x); acc.y = f2tf32(acc.y);
    acc.z = f2tf32(acc.z); acc.w = f2tf32(acc.w);
    *(float4*)(out + o) = acc;
}

// ---------------- tf32 warp-MMA fused 3-term GEMM, cp.async TRIPLE-buffered ----------------
// BM=128, BN=128, BK=32; 8 warps (2x4), warp tile 64x32; 256 threads.
// R12-proven scalar-LDS fragment feed; 3 stages -> one __syncthreads per chunk.
#define GST 36
template <int FOUT, int X0ID, int X1ID, int X2ID, int OID, bool RX0>
__global__ void __launch_bounds__(256) gemm3_mma_kernel(
    const float* __restrict__ ext, const float* __restrict__ bias) {
    const float* X0 = bufptr<X0ID>(ext);
    const float* X1 = bufptr<X1ID>(ext);
    const float* X2 = bufptr<X2ID>(ext);
    const float* Wt = (FOUT == NFEAT) ? g_Wt1 : g_Wt2;
    float* out = bufptr<OID>(ext);

    __shared__ __align__(16) float As[3][128 * GST];
    __shared__ __align__(16) float Bs[3][128 * GST];

    int tid  = threadIdx.x;
    int wid  = tid >> 5;
    int lane = tid & 31;
    int wm = (wid & 1) * 64;
    int wn = (wid >> 1) * 32;
    int row0 = blockIdx.x * 128;
    int col0 = blockIdx.y * 128;
    int gp = lane >> 2;
    int tg = lane & 3;

    const uint32_t asb = smem_u32(As);
    const uint32_t bsb = smem_u32(Bs);

    float acc[4][4][4];
#pragma unroll
    for (int i = 0; i < 4; i++)
#pragma unroll
        for (int j = 0; j < 4; j++)
#pragma unroll
            for (int r = 0; r < 4; r++) acc[i][j][r] = 0.f;

    auto LOAD = [&](int ch, int buf) {
        int t  = ch >> 2;
        int k0 = (ch & 3) * 32;
        const float* Xp = (t == 0) ? X0 : ((t == 1) ? X1 : X2);
        uint32_t ab = asb + (uint32_t)buf * 128 * GST * 4;
        uint32_t bb = bsb + (uint32_t)buf * 128 * GST * 4;
#pragma unroll
        for (int i = 0; i < 4; i++) {
            int idx = tid + i * 256;
            int r   = idx >> 3;
            int c4  = (idx & 7) * 4;
            int grow = row0 + r;
            int sz = (grow < NNODES) ? 16 : 0;
            cp16(ab + (r * GST + c4) * 4, Xp + (size_t)grow * NFEAT + k0 + c4, sz);
            cp16(bb + (r * GST + c4) * 4,
                 Wt + (size_t)(col0 + r) * CF + t * NFEAT + k0 + c4, 16);
        }
        CP_COMMIT();
    };

    LOAD(0, 0);
    LOAD(1, 1);
    for (int ch = 0; ch < 12; ch++) {
        int buf = ch % 3;
        if (ch < 11) {
            CP_WAIT(1);     // LOAD(ch) complete (LOAD(ch+1) may still be in flight)
        } else {
            CP_WAIT(0);
        }
        __syncthreads();    // all warps finished chunk ch-1 compute; safe to overwrite buf (ch+2)%3
        if (ch < 10) LOAD(ch + 2, (ch + 2) % 3);

        const float* A = As[buf];
        const float* B = Bs[buf];
        const bool rnd = RX0 && (ch < 4);
#pragma unroll
        for (int ks = 0; ks < 4; ks++) {
            int kc = ks * 8 + tg;
            uint32_t afr[4][4];
#pragma unroll
            for (int mt = 0; mt < 4; mt++) {
                int m = wm + mt * 16 + gp;
                float a0 = A[m * GST + kc];
                float a1 = A[(m + 8) * GST + kc];
                float a2 = A[m * GST + kc + 4];
                float a3 = A[(m + 8) * GST + kc + 4];
                if (rnd) { a0 = f2tf32(a0); a1 = f2tf32(a1); a2 = f2tf32(a2); a3 = f2tf32(a3); }
                afr[mt][0] = __float_as_uint(a0);
                afr[mt][1] = __float_as_uint(a1);
                afr[mt][2] = __float_as_uint(a2);
                afr[mt][3] = __float_as_uint(a3);
            }
            uint32_t bfr[4][2];
#pragma unroll
            for (int nt = 0; nt < 4; nt++) {
                int n = wn + nt * 8 + gp;
                bfr[nt][0] = __float_as_uint(B[n * GST + kc]);
                bfr[nt][1] = __float_as_uint(B[n * GST + kc + 4]);
            }
#pragma unroll
            for (int mt = 0; mt < 4; mt++)
#pragma unroll
                for (int nt = 0; nt < 4; nt++)
                    mma_tf32(acc[mt][nt], afr[mt], bfr[nt]);
        }
    }

#pragma unroll
    for (int mt = 0; mt < 4; mt++) {
#pragma unroll
        for (int nt = 0; nt < 4; nt++) {
            int gcol = col0 + wn + nt * 8 + 2 * tg;
            float2 bv = *(const float2*)(bias + gcol);
            int r0 = row0 + wm + mt * 16 + gp;
            if (r0 < NNODES) {
                float2 o0;
                o0.x = fmaxf(acc[mt][nt][0] + bv.x, 0.f);
                o0.y = fmaxf(acc[mt][nt][1] + bv.y, 0.f);
                if (OID == 3) { o0.x = f2tf32(o0.x); o0.y = f2tf32(o0.y); }
                *(float2*)(out + (size_t)r0 * FOUT + gcol) = o0;
            }
            int r1 = r0 + 8;
            if (r1 < NNODES) {
                float2 o1;
                o1.x = fmaxf(acc[mt][nt][2] + bv.x, 0.f);
                o1.y = fmaxf(acc[mt][nt][3] + bv.y, 0.f);
                if (OID == 3) { o1.x = f2tf32(o1.x); o1.y = f2tf32(o1.y); }
                *(float2*)(out + (size_t)r1 * FOUT + gcol) = o1;
            }
        }
    }
}

// ---------------- fused tail: pool -> fc1 -> fc2 ----------------
__global__ void __launch_bounds__(512) tail_kernel(
    const float* __restrict__ feat, const void* __restrict__ batch,
    const float* __restrict__ fc1_w, const float* __restrict__ fc1_b,
    const float* __restrict__ fc2_w, const float* __restrict__ fc2_b,
    float* __restrict__ out) {
    __shared__ float sp[CF];
    __shared__ float sh[HID];
    __shared__ int s_lo, s_hi;
    int b = blockIdx.x;
    int tid = threadIdx.x;

    if (tid < 2) {
        int target = b + tid;
        int is64 = g_is64;
        int lo = 0, hi = NNODES;
        while (lo < hi) {
            int mid = (lo + hi) >> 1;
            int v = load_idx(batch, mid, is64);
            if (v < target) lo = mid + 1;
            else hi = mid;
        }
        if (tid == 0) s_lo = lo; else s_hi = lo;
    }
    __syncthreads();
    int lo = s_lo, hi = s_hi;
    float inv = 1.f / fmaxf((float)(hi - lo), 1.f);

    if (tid < CF) {
        float s = 0.f;
        if (tid < F2) {
            for (int r = lo; r < hi; r++) s += g_gx2[(size_t)r * F2 + tid];
        } else {
            int cc = tid - F2;
            for (int r = lo; r < hi; r++) s += feat[(size_t)r * NFEAT + cc];
        }
        sp[tid] = s * inv;
    }
    __syncthreads();

    {
        float s = fc1_b[tid];
        for (int k = 0; k < CF; k++) s += sp[k] * fc1_w[(size_t)k * HID + tid];
        sh[tid] = fmaxf(s, 0.f);
    }
    __syncthreads();

    if (tid < NOUT) {
        float s = fc2_b[tid];
        for (int k = 0; k < HID; k++) s += sh[k] * fc2_w[(size_t)k * NOUT + tid];
        out[b * NOUT + tid] = s;
    }
}

// ---------------- launch ----------------
extern "C" void kernel_launch(void* const* d_in, const int* in_sizes, int n_in,
                              void* d_out, int out_size) {
    const float* feature = nullptr;
    const void* ei = nullptr;
    const void* pbatch = nullptr;
    const float *W1 = nullptr, *b1 = nullptr, *W2 = nullptr, *b2 = nullptr;
    const float *fc1_w = nullptr, *fc1_b = nullptr, *fc2_w = nullptr, *fc2_b = nullptr;
    int seen128 = 0;
    for (int i = 0; i < n_in; i++) {
        switch (in_sizes[i]) {
            case 6400000: feature = (const float*)d_in[i]; break;
            case 1200000: ei      = d_in[i]; break;
            case 50000:   pbatch  = d_in[i]; break;
            case 49152:   W1      = (const float*)d_in[i]; break;
            case 98304:   W2      = (const float*)d_in[i]; break;
            case 196608:  fc1_w   = (const float*)d_in[i]; break;
            case 512:     fc1_b   = (const float*)d_in[i]; break;
            case 65536:   fc2_w   = (const float*)d_in[i]; break;
            case 256:     b2      = (const float*)d_in[i]; break;
            case 128:
                if (seen128++ == 0) b1 = (const float*)d_in[i];
                else                fc2_b = (const float*)d_in[i];
                break;
            default: break;
        }
    }
    float* out = (float*)d_out;

    csr_kernel<<<NB, 1024>>>(ei, W1, W2);

    const int PROP_BLOCKS = (NNODES * 32 + 255) / 256;

    // ---- conv1 ----
    prop_kernel<0, -1, 1><<<PROP_BLOCKS, 256>>>(feature, 1.f);
    prop_kernel<1, 0, 2><<<PROP_BLOCKS, 256>>>(feature, 2.f);
    {
        dim3 grid((NNODES + 127) / 128, NFEAT / 128);
        gemm3_mma_kernel<NFEAT, 0, 1, 2, 3, true><<<grid, 256>>>(feature, b1);
    }

    // ---- conv2 ----
    prop_kernel<3, -1, 1><<<PROP_BLOCKS, 256>>>(feature, 1.f);
    prop_kernel<1, 3, 2><<<PROP_BLOCKS, 256>>>(feature, 2.f);
    {
        dim3 grid((NNODES + 127) / 128, F2 / 128);
        gemm3_mma_kernel<F2, 3, 1, 2, 4, false><<<grid, 256>>>(feature, b2);
    }

    // ---- fused pool + fc1 + fc2 ----
    tail_kernel<<<NGR, 512>>>(feature, pbatch, fc1_w, fc1_b, fc2_w, fc2_b, out);
}

// round 15
// speedup vs baseline: 1.1058x; 1.1058x over previous
#include <cuda_runtime.h>
#include <cuda_bf16.h>
#include <cstdint>

#define NNODES 50000
#define NEDGES 600000
#define NFEAT  128
#define F2     256
#define CF     384
#define HID    512
#define NOUT   128
#define NGR    128
#define NBLK   49          // ceil(50000/1024)
#define NB     128         // blocks in fused CSR kernel (co-resident: 296 slots)

__device__ __forceinline__ float f2tf32(float x) {
    float y;
    asm("cvt.rna.tf32.f32 %0, %1;" : "=f"(y) : "f"(x));
    return y;
}

__device__ __forceinline__ void mma_tf32(float c[4], const uint32_t a[4], const uint32_t b[2]) {
    asm volatile(
        "mma.sync.aligned.m16n8k8.row.col.f32.tf32.tf32.f32 "
        "{%0,%1,%2,%3}, {%4,%5,%6,%7}, {%8,%9}, {%0,%1,%2,%3};"
        : "+f"(c[0]), "+f"(c[1]), "+f"(c[2]), "+f"(c[3])
        : "r"(a[0]), "r"(a[1]), "r"(a[2]), "r"(a[3]), "r"(b[0]), "r"(b[1]));
}

__device__ __forceinline__ uint32_t smem_u32(const void* p) {
    uint32_t a;
    asm("{ .reg .u64 t; cvta.to.shared.u64 t, %1; cvt.u32.u64 %0, t; }" : "=r"(a) : "l"(p));
    return a;
}

__device__ __forceinline__ void cp16(uint32_t dst, const void* src, int sz) {
    asm volatile("cp.async.ca.shared.global [%0], [%1], 16, %2;"
                 :: "r"(dst), "l"(src), "r"(sz) : "memory");
}
#define CP_COMMIT() asm volatile("cp.async.commit_group;" ::: "memory")
#define CP_WAIT(N)  asm volatile("cp.async.wait_group %0;" :: "n"(N) : "memory")

// ---------------- scratch ----------------
__device__ __align__(256) int   g_scnt[NNODES];
__device__ __align__(256) float g_dinv[NNODES];
__device__ __align__(256) int   g_cnt[NNODES];
__device__ __align__(256) int   g_rowptr[NNODES + 1];
__device__ __align__(256) int   g_cursor[NNODES];
__device__ __align__(256) int   g_bsum[NBLK];
__device__ __align__(256) int   g_csr_src[NEDGES];
__device__ __align__(256) float g_csr_w[NEDGES];
__device__ __align__(256) float g_Tx1[(size_t)NNODES * NFEAT];
__device__ __align__(256) float g_Tx2[(size_t)NNODES * NFEAT];
__device__ __align__(256) float g_gx1[(size_t)NNODES * NFEAT];
__device__ __align__(256) float g_gx2[(size_t)NNODES * F2];
__device__ __align__(256) float g_Wt1[NFEAT * CF];
__device__ __align__(256) float g_Wt2[F2 * CF];
__device__ int g_is64;

// grid barrier state (fused CSR kernel)
__device__ int g_bar_count;
__device__ volatile int g_bar_sense;

__device__ __forceinline__ void grid_barrier(int target) {
    __syncthreads();
    if (threadIdx.x == 0) {
        __threadfence();
        if (atomicAdd(&g_bar_count, 1) == NB - 1) {
            atomicExch(&g_bar_count, 0);
            __threadfence();
            g_bar_sense = target;
        } else {
            while (g_bar_sense < target) {}
        }
        __threadfence();
    }
    __syncthreads();
}

template <int ID>
__device__ __forceinline__ float* bufptr(const float* ext) {
    if (ID == 1) return g_Tx1;
    if (ID == 2) return g_Tx2;
    if (ID == 3) return g_gx1;
    if (ID == 4) return g_gx2;
    return (float*)ext;
}

__device__ __forceinline__ int load_idx(const void* p, long long i, int is64) {
    if (is64) return (int)((const long long*)p)[i];
    return ((const int*)p)[i];
}

// ---------------- fused CSR build ----------------
__global__ void __launch_bounds__(1024) csr_kernel(const void* __restrict__ ei,
                                                   const float* __restrict__ W1,
                                                   const float* __restrict__ W2) {
    __shared__ int warpsum[32];
    __shared__ int sb[64];
    int tid = threadIdx.x;
    int b = blockIdx.x;
    int gt = b * 1024 + tid;
    int wid = tid >> 5, lane = tid & 31;
    int base = g_bar_sense;

    // ---- P0: zero counters, dtype detect, weight transpose ----
    if (gt < NNODES) { g_scnt[gt] = 0; g_cnt[gt] = 0; }
    if (gt == 0) {
        const int* p = (const int*)ei;
        int orv = 0;
        for (int j = 0; j < 64; j++) orv |= p[2 * j + 1];
        g_is64 = (orv == 0) ? 1 : 0;
    }
    for (int i = gt; i < CF * NFEAT; i += NB * 1024) {
        int kk = i / NFEAT, n = i % NFEAT;
        g_Wt1[(size_t)n * CF + kk] = f2tf32(W1[i]);
    }
    for (int i = gt; i < CF * F2; i += NB * 1024) {
        int kk = i / F2, n = i % F2;
        g_Wt2[(size_t)n * CF + kk] = f2tf32(W2[i]);
    }
    grid_barrier(base + 1);

    // ---- P1: degree counts ----
    int is64 = __ldcg(&g_is64);
    for (int e = gt; e < NEDGES; e += NB * 1024) {
        int s = load_idx(ei, e, is64);
        int d = load_idx(ei, (long long)NEDGES + e, is64);
        if (s < 0 || s >= NNODES || d < 0 || d >= NNODES) continue;
        atomicAdd(&g_scnt[s], 1);
        atomicAdd(&g_cnt[d], 1);
    }
    grid_barrier(base + 2);

    // ---- P2: dinv + per-chunk exclusive scan ----
    if (gt < NNODES) {
        float dg = (float)__ldcg(&g_scnt[gt]);
        g_dinv[gt] = (dg > 0.f) ? rsqrtf(dg) : 0.f;
    }
    {
        int v = (b < NBLK && gt < NNODES) ? __ldcg(&g_cnt[gt]) : 0;
        int x = v;
#pragma unroll
        for (int off = 1; off < 32; off <<= 1) {
            int n = __shfl_up_sync(0xFFFFFFFFu, x, off);
            if (lane >= off) x += n;
        }
        if (lane == 31) warpsum[wid] = x;
        __syncthreads();
        if (wid == 0) {
            int y = warpsum[lane];
#pragma unroll
            for (int off = 1; off < 32; off <<= 1) {
                int n = __shfl_up_sync(0xFFFFFFFFu, y, off);
                if (lane >= off) y += n;
            }
            warpsum[lane] = y;
        }
        __syncthreads();
        int incl = x + (wid > 0 ? warpsum[wid - 1] : 0);
        if (b < NBLK) {
            if (gt < NNODES) g_rowptr[gt] = incl - v;
            if (tid == 1023) g_bsum[b] = incl;
        }
    }
    grid_barrier(base + 3);

    // ---- P3: block-sum scan + finalize rowptr/cursor ----
    if (tid < 64) sb[tid] = (tid < NBLK) ? __ldcg(&g_bsum[tid]) : 0;
    __syncthreads();
#pragma unroll
    for (int off = 1; off < 64; off <<= 1) {
        int t = (tid < 64 && tid >= off) ? sb[tid - off] : 0;
        __syncthreads();
        if (tid < 64) sb[tid] += t;
        __syncthreads();
    }
    if (b == 0 && tid == 0) g_rowptr[NNODES] = sb[NBLK - 1];
    if (gt < NNODES) {
        int s_off = (b > 0 && b < NBLK) ? sb[b - 1] : 0;
        int o = g_rowptr[gt] + s_off;
        g_rowptr[gt] = o;
        g_cursor[gt] = o;
    }
    grid_barrier(base + 4);

    // ---- P4: scatter edges into CSR ----
    for (int e = gt; e < NEDGES; e += NB * 1024) {
        int s = load_idx(ei, e, is64);
        int d = load_idx(ei, (long long)NEDGES + e, is64);
        if (s < 0 || s >= NNODES || d < 0 || d >= NNODES) continue;
        float w = -__ldcg(&g_dinv[s]) * __ldcg(&g_dinv[d]);
        int pos = atomicAdd(&g_cursor[d], 1);
        g_csr_src[pos] = s;
        g_csr_w[pos]   = w;
    }
}

// ---------------- sparse propagation (outputs tf32-rounded; unroll x4) ----------------
template <int XID, int PID, int OID>
__global__ void prop_kernel(const float* __restrict__ ext, float alpha) {
    const float* x = bufptr<XID>(ext);
    float* out = bufptr<OID>(ext);
    int warp = (blockIdx.x * blockDim.x + threadIdx.x) >> 5;
    if (warp >= NNODES) return;
    int lane = threadIdx.x & 31;
    int beg = g_rowptr[warp];
    int end = g_rowptr[warp + 1];
    float4 acc = make_float4(0.f, 0.f, 0.f, 0.f);
    int j = beg;
    for (; j + 4 <= end; j += 4) {
        int s0 = g_csr_src[j],     s1 = g_csr_src[j + 1];
        int s2 = g_csr_src[j + 2], s3 = g_csr_src[j + 3];
        float w0 = g_csr_w[j],     w1 = g_csr_w[j + 1];
        float w2 = g_csr_w[j + 2], w3 = g_csr_w[j + 3];
        const float4 v0 = *(const float4*)(x + (size_t)s0 * NFEAT + lane * 4);
        const float4 v1 = *(const float4*)(x + (size_t)s1 * NFEAT + lane * 4);
        const float4 v2 = *(const float4*)(x + (size_t)s2 * NFEAT + lane * 4);
        const float4 v3 = *(const float4*)(x + (size_t)s3 * NFEAT + lane * 4);
        acc.x += w0 * v0.x + w1 * v1.x + w2 * v2.x + w3 * v3.x;
        acc.y += w0 * v0.y + w1 * v1.y + w2 * v2.y + w3 * v3.y;
        acc.z += w0 * v0.z + w1 * v1.z + w2 * v2.z + w3 * v3.z;
        acc.w += w0 * v0.w + w1 * v1.w + w2 * v2.w + w3 * v3.w;
    }
    for (; j < end; j++) {
        int s   = g_csr_src[j];
        float w = g_csr_w[j];
        const float4 v = *(const float4*)(x + (size_t)s * NFEAT + lane * 4);
        acc.x += w * v.x; acc.y += w * v.y; acc.z += w * v.z; acc.w += w * v.w;
    }
    size_t o = (size_t)warp * NFEAT + lane * 4;
    if (PID >= 0) {
        const float* xprev = bufptr<(PID >= 0 ? PID : 0)>(ext);
        const float4 p = *(const float4*)(xprev + o);
        acc.x = alpha * acc.x - p.x;
        acc.y = alpha * acc.y - p.y;
        acc.z = alpha * acc.z - p.z;
        acc.w = alpha * acc.w - p.w;
    }
    acc.x = f2tf32(acc.x); acc.y = f2tf32(acc.y);
    acc.z = f2tf32(acc.z); acc.w = f2tf32(acc.w);
    *(float4*)(out + o) = acc;
}

// ---------------- tf32 warp-MMA fused 3-term GEMM, cp.async double-buffered (R12) ----------------
// BM=128, BN=128, BK=32; 8 warps (2x4), warp tile 64x32; 256 threads.
#define GST 36
template <int FOUT, int X0ID, int X1ID, int X2ID, int OID, bool RX0>
__global__ void __launch_bounds__(256) gemm3_mma_kernel(
    const float* __restrict__ ext, const float* __restrict__ bias) {
    const float* X0 = bufptr<X0ID>(ext);
    const float* X1 = bufptr<X1ID>(ext);
    const float* X2 = bufptr<X2ID>(ext);
    const float* Wt = (FOUT == NFEAT) ? g_Wt1 : g_Wt2;
    float* out = bufptr<OID>(ext);

    __shared__ __align__(16) float As[2][128 * GST];
    __shared__ __align__(16) float Bs[2][128 * GST];

    int tid  = threadIdx.x;
    int wid  = tid >> 5;
    int lane = tid & 31;
    int wm = (wid & 1) * 64;
    int wn = (wid >> 1) * 32;
    int row0 = blockIdx.x * 128;
    int col0 = blockIdx.y * 128;
    int gp = lane >> 2;
    int tg = lane & 3;

    const uint32_t asb = smem_u32(As);
    const uint32_t bsb = smem_u32(Bs);

    float acc[4][4][4];
#pragma unroll
    for (int i = 0; i < 4; i++)
#pragma unroll
        for (int j = 0; j < 4; j++)
#pragma unroll
            for (int r = 0; r < 4; r++) acc[i][j][r] = 0.f;

    auto LOAD = [&](int ch, int buf) {
        int t  = ch >> 2;
        int k0 = (ch & 3) * 32;
        const float* Xp = (t == 0) ? X0 : ((t == 1) ? X1 : X2);
        uint32_t ab = asb + (uint32_t)buf * 128 * GST * 4;
        uint32_t bb = bsb + (uint32_t)buf * 128 * GST * 4;
#pragma unroll
        for (int i = 0; i < 4; i++) {
            int idx = tid + i * 256;
            int r   = idx >> 3;
            int c4  = (idx & 7) * 4;
            int grow = row0 + r;
            int sz = (grow < NNODES) ? 16 : 0;
            cp16(ab + (r * GST + c4) * 4, Xp + (size_t)grow * NFEAT + k0 + c4, sz);
            cp16(bb + (r * GST + c4) * 4,
                 Wt + (size_t)(col0 + r) * CF + t * NFEAT + k0 + c4, 16);
        }
        CP_COMMIT();
    };

    LOAD(0, 0);
    for (int ch = 0; ch < 12; ch++) {
        int buf = ch & 1;
        if (ch < 11) {
            LOAD(ch + 1, buf ^ 1);
            CP_WAIT(1);
        } else {
            CP_WAIT(0);
        }
        __syncthreads();

        const float* A = As[buf];
        const float* B = Bs[buf];
        const bool rnd = RX0 && (ch < 4);
#pragma unroll
        for (int ks = 0; ks < 4; ks++) {
            int kc = ks * 8 + tg;
            uint32_t afr[4][4];
#pragma unroll
            for (int mt = 0; mt < 4; mt++) {
                int m = wm + mt * 16 + gp;
                float a0 = A[m * GST + kc];
                float a1 = A[(m + 8) * GST + kc];
                float a2 = A[m * GST + kc + 4];
                float a3 = A[(m + 8) * GST + kc + 4];
                if (rnd) { a0 = f2tf32(a0); a1 = f2tf32(a1); a2 = f2tf32(a2); a3 = f2tf32(a3); }
                afr[mt][0] = __float_as_uint(a0);
                afr[mt][1] = __float_as_uint(a1);
                afr[mt][2] = __float_as_uint(a2);
                afr[mt][3] = __float_as_uint(a3);
            }
            uint32_t bfr[4][2];
#pragma unroll
            for (int nt = 0; nt < 4; nt++) {
                int n = wn + nt * 8 + gp;
                bfr[nt][0] = __float_as_uint(B[n * GST + kc]);
                bfr[nt][1] = __float_as_uint(B[n * GST + kc + 4]);
            }
#pragma unroll
            for (int mt = 0; mt < 4; mt++)
#pragma unroll
                for (int nt = 0; nt < 4; nt++)
                    mma_tf32(acc[mt][nt], afr[mt], bfr[nt]);
        }
        __syncthreads();
    }

#pragma unroll
    for (int mt = 0; mt < 4; mt++) {
#pragma unroll
        for (int nt = 0; nt < 4; nt++) {
            int gcol = col0 + wn + nt * 8 + 2 * tg;
            float2 bv = *(const float2*)(bias + gcol);
            int r0 = row0 + wm + mt * 16 + gp;
            if (r0 < NNODES) {
                float2 o0;
                o0.x = fmaxf(acc[mt][nt][0] + bv.x, 0.f);
                o0.y = fmaxf(acc[mt][nt][1] + bv.y, 0.f);
                if (OID == 3) { o0.x = f2tf32(o0.x); o0.y = f2tf32(o0.y); }
                *(float2*)(out + (size_t)r0 * FOUT + gcol) = o0;
            }
            int r1 = r0 + 8;
            if (r1 < NNODES) {
                float2 o1;
                o1.x = fmaxf(acc[mt][nt][2] + bv.x, 0.f);
                o1.y = fmaxf(acc[mt][nt][3] + bv.y, 0.f);
                if (OID == 3) { o1.x = f2tf32(o1.x); o1.y = f2tf32(o1.y); }
                *(float2*)(out + (size_t)r1 * FOUT + gcol) = o1;
            }
        }
    }
}

// ---------------- fused tail: pool -> fc1 -> fc2 ----------------
__global__ void __launch_bounds__(512) tail_kernel(
    const float* __restrict__ feat, const void* __restrict__ batch,
    const float* __restrict__ fc1_w, const float* __restrict__ fc1_b,
    const float* __restrict__ fc2_w, const float* __restrict__ fc2_b,
    float* __restrict__ out) {
    __shared__ float sp[CF];
    __shared__ float sh[HID];
    __shared__ int s_lo, s_hi;
    int b = blockIdx.x;
    int tid = threadIdx.x;

    if (tid < 2) {
        int target = b + tid;
        int is64 = g_is64;
        int lo = 0, hi = NNODES;
        while (lo < hi) {
            int mid = (lo + hi) >> 1;
            int v = load_idx(batch, mid, is64);
            if (v < target) lo = mid + 1;
            else hi = mid;
        }
        if (tid == 0) s_lo = lo; else s_hi = lo;
    }
    __syncthreads();
    int lo = s_lo, hi = s_hi;
    float inv = 1.f / fmaxf((float)(hi - lo), 1.f);

    if (tid < CF) {
        float s = 0.f;
        if (tid < F2) {
            for (int r = lo; r < hi; r++) s += g_gx2[(size_t)r * F2 + tid];
        } else {
            int cc = tid - F2;
            for (int r = lo; r < hi; r++) s += feat[(size_t)r * NFEAT + cc];
        }
        sp[tid] = s * inv;
    }
    __syncthreads();

    {
        float s = fc1_b[tid];
        for (int k = 0; k < CF; k++) s += sp[k] * fc1_w[(size_t)k * HID + tid];
        sh[tid] = fmaxf(s, 0.f);
    }
    __syncthreads();

    if (tid < NOUT) {
        float s = fc2_b[tid];
        for (int k = 0; k < HID; k++) s += sh[k] * fc2_w[(size_t)k * NOUT + tid];
        out[b * NOUT + tid] = s;
    }
}

// ---------------- launch ----------------
extern "C" void kernel_launch(void* const* d_in, const int* in_sizes, int n_in,
                              void* d_out, int out_size) {
    const float* feature = nullptr;
    const void* ei = nullptr;
    const void* pbatch = nullptr;
    const float *W1 = nullptr, *b1 = nullptr, *W2 = nullptr, *b2 = nullptr;
    const float *fc1_w = nullptr, *fc1_b = nullptr, *fc2_w = nullptr, *fc2_b = nullptr;
    int seen128 = 0;
    for (int i = 0; i < n_in; i++) {
        switch (in_sizes[i]) {
            case 6400000: feature = (const float*)d_in[i]; break;
            case 1200000: ei      = d_in[i]; break;
            case 50000:   pbatch  = d_in[i]; break;
            case 49152:   W1      = (const float*)d_in[i]; break;
            case 98304:   W2      = (const float*)d_in[i]; break;
            case 196608:  fc1_w   = (const float*)d_in[i]; break;
            case 512:     fc1_b   = (const float*)d_in[i]; break;
            case 65536:   fc2_w   = (const float*)d_in[i]; break;
            case 256:     b2      = (const float*)d_in[i]; break;
            case 128:
                if (seen128++ == 0) b1 = (const float*)d_in[i];
                else                fc2_b = (const float*)d_in[i];
                break;
            default: break;
        }
    }
    float* out = (float*)d_out;

    csr_kernel<<<NB, 1024>>>(ei, W1, W2);

    const int PROP_BLOCKS = (NNODES * 32 + 255) / 256;

    // ---- conv1 ----
    prop_kernel<0, -1, 1><<<PROP_BLOCKS, 256>>>(feature, 1.f);
    prop_kernel<1, 0, 2><<<PROP_BLOCKS, 256>>>(feature, 2.f);
    {
        dim3 grid((NNODES + 127) / 128, NFEAT / 128);
        gemm3_mma_kernel<NFEAT, 0, 1, 2, 3, true><<<grid, 256>>>(feature, b1);
    }

    // ---- conv2 ----
    prop_kernel<3, -1, 1><<<PROP_BLOCKS, 256>>>(feature, 1.f);
    prop_kernel<1, 3, 2><<<PROP_BLOCKS, 256>>>(feature, 2.f);
    {
        dim3 grid((NNODES + 127) / 128, F2 / 128);
        gemm3_mma_kernel<F2, 3, 1, 2, 4, false><<<grid, 256>>>(feature, b2);
    }

    // ---- fused pool + fc1 + fc2 ----
    tail_kernel<<<NGR, 512>>>(feature, pbatch, fc1_w, fc1_b, fc2_w, fc2_b, out);
}

// round 16
// speedup vs baseline: 1.1349x; 1.0263x over previous
#include <cuda_runtime.h>
#include <cuda_bf16.h>
#include <cuda_fp16.h>
#include <cstdint>

#define NNODES 50000
#define NEDGES 600000
#define NFEAT  128
#define F2     256
#define CF     384
#define HID    512
#define NOUT   128
#define NGR    128
#define NBLK   49          // ceil(50000/1024)
#define NB     128         // blocks in fused CSR kernel (co-resident: 296 slots)

__device__ __forceinline__ float f2tf32(float x) {
    float y;
    asm("cvt.rna.tf32.f32 %0, %1;" : "=f"(y) : "f"(x));
    return y;
}

__device__ __forceinline__ void mma_tf32(float c[4], const uint32_t a[4], const uint32_t b[2]) {
    asm volatile(
        "mma.sync.aligned.m16n8k8.row.col.f32.tf32.tf32.f32 "
        "{%0,%1,%2,%3}, {%4,%5,%6,%7}, {%8,%9}, {%0,%1,%2,%3};"
        : "+f"(c[0]), "+f"(c[1]), "+f"(c[2]), "+f"(c[3])
        : "r"(a[0]), "r"(a[1]), "r"(a[2]), "r"(a[3]), "r"(b[0]), "r"(b[1]));
}

__device__ __forceinline__ uint32_t smem_u32(const void* p) {
    uint32_t a;
    asm("{ .reg .u64 t; cvta.to.shared.u64 t, %1; cvt.u32.u64 %0, t; }" : "=r"(a) : "l"(p));
    return a;
}

__device__ __forceinline__ void cp16(uint32_t dst, const void* src, int sz) {
    asm volatile("cp.async.ca.shared.global [%0], [%1], 16, %2;"
                 :: "r"(dst), "l"(src), "r"(sz) : "memory");
}
#define CP_COMMIT() asm volatile("cp.async.commit_group;" ::: "memory")
#define CP_WAIT(N)  asm volatile("cp.async.wait_group %0;" :: "n"(N) : "memory")

// ---------------- scratch ----------------
__device__ __align__(256) int   g_scnt[NNODES];
__device__ __align__(256) float g_dinv[NNODES];
__device__ __align__(256) int   g_cnt[NNODES];
__device__ __align__(256) int   g_rowptr[NNODES + 1];
__device__ __align__(256) int   g_cursor[NNODES];
__device__ __align__(256) int   g_bsum[NBLK];
__device__ __align__(256) int   g_csr_src[NEDGES];
__device__ __align__(256) float g_csr_w[NEDGES];
__device__ __align__(256) float g_Tx1[(size_t)NNODES * NFEAT];
__device__ __align__(256) float g_Tx2[(size_t)NNODES * NFEAT];
__device__ __align__(256) float g_gx1[(size_t)NNODES * NFEAT];
__device__ __align__(256) float g_gx2[(size_t)NNODES * F2];
__device__ __align__(256) __half g_x16[(size_t)NNODES * NFEAT];   // fp16 feature
__device__ __align__(256) __half g_Tx1h[(size_t)NNODES * NFEAT];  // fp16 Tx1
__device__ __align__(256) __half g_gx1h[(size_t)NNODES * NFEAT];  // fp16 gx1
__device__ __align__(256) float g_Wt1[NFEAT * CF];
__device__ __align__(256) float g_Wt2[F2 * CF];
__device__ int g_is64;

// grid barrier state (fused CSR kernel)
__device__ int g_bar_count;
__device__ volatile int g_bar_sense;

__device__ __forceinline__ void grid_barrier(int target) {
    __syncthreads();
    if (threadIdx.x == 0) {
        __threadfence();
        if (atomicAdd(&g_bar_count, 1) == NB - 1) {
            atomicExch(&g_bar_count, 0);
            __threadfence();
            g_bar_sense = target;
        } else {
            while (g_bar_sense < target) {}
        }
        __threadfence();
    }
    __syncthreads();
}

template <int ID>
__device__ __forceinline__ float* bufptr(const float* ext) {
    if (ID == 1) return g_Tx1;
    if (ID == 2) return g_Tx2;
    if (ID == 3) return g_gx1;
    if (ID == 4) return g_gx2;
    return (float*)ext;
}

__device__ __forceinline__ int load_idx(const void* p, long long i, int is64) {
    if (is64) return (int)((const long long*)p)[i];
    return ((const int*)p)[i];
}

// ---------------- fused CSR build (+ fp16 feature copy) ----------------
__global__ void __launch_bounds__(1024) csr_kernel(const void* __restrict__ ei,
                                                   const float* __restrict__ W1,
                                                   const float* __restrict__ W2,
                                                   const float* __restrict__ feat) {
    __shared__ int warpsum[32];
    __shared__ int sb[64];
    int tid = threadIdx.x;
    int b = blockIdx.x;
    int gt = b * 1024 + tid;
    int wid = tid >> 5, lane = tid & 31;
    int base = g_bar_sense;

    // ---- P0: zero counters, dtype detect, weight transpose, fp16 feature copy ----
    if (gt < NNODES) { g_scnt[gt] = 0; g_cnt[gt] = 0; }
    if (gt == 0) {
        const int* p = (const int*)ei;
        int orv = 0;
        for (int j = 0; j < 64; j++) orv |= p[2 * j + 1];
        g_is64 = (orv == 0) ? 1 : 0;
    }
    for (int i = gt; i < CF * NFEAT; i += NB * 1024) {
        int kk = i / NFEAT, n = i % NFEAT;
        g_Wt1[(size_t)n * CF + kk] = f2tf32(W1[i]);
    }
    for (int i = gt; i < CF * F2; i += NB * 1024) {
        int kk = i / F2, n = i % F2;
        g_Wt2[(size_t)n * CF + kk] = f2tf32(W2[i]);
    }
    {
        const float4* f4 = (const float4*)feat;
        __half2* h2 = (__half2*)g_x16;
        for (int i = gt; i < NNODES * NFEAT / 4; i += NB * 1024) {
            float4 v = f4[i];
            h2[i * 2]     = __floats2half2_rn(v.x, v.y);
            h2[i * 2 + 1] = __floats2half2_rn(v.z, v.w);
        }
    }
    grid_barrier(base + 1);

    // ---- P1: degree counts ----
    int is64 = __ldcg(&g_is64);
    for (int e = gt; e < NEDGES; e += NB * 1024) {
        int s = load_idx(ei, e, is64);
        int d = load_idx(ei, (long long)NEDGES + e, is64);
        if (s < 0 || s >= NNODES || d < 0 || d >= NNODES) continue;
        atomicAdd(&g_scnt[s], 1);
        atomicAdd(&g_cnt[d], 1);
    }
    grid_barrier(base + 2);

    // ---- P2: dinv + per-chunk exclusive scan ----
    if (gt < NNODES) {
        float dg = (float)__ldcg(&g_scnt[gt]);
        g_dinv[gt] = (dg > 0.f) ? rsqrtf(dg) : 0.f;
    }
    {
        int v = (b < NBLK && gt < NNODES) ? __ldcg(&g_cnt[gt]) : 0;
        int x = v;
#pragma unroll
        for (int off = 1; off < 32; off <<= 1) {
            int n = __shfl_up_sync(0xFFFFFFFFu, x, off);
            if (lane >= off) x += n;
        }
        if (lane == 31) warpsum[wid] = x;
        __syncthreads();
        if (wid == 0) {
            int y = warpsum[lane];
#pragma unroll
            for (int off = 1; off < 32; off <<= 1) {
                int n = __shfl_up_sync(0xFFFFFFFFu, y, off);
                if (lane >= off) y += n;
            }
            warpsum[lane] = y;
        }
        __syncthreads();
        int incl = x + (wid > 0 ? warpsum[wid - 1] : 0);
        if (b < NBLK) {
            if (gt < NNODES) g_rowptr[gt] = incl - v;
            if (tid == 1023) g_bsum[b] = incl;
        }
    }
    grid_barrier(base + 3);

    // ---- P3: block-sum scan + finalize rowptr/cursor ----
    if (tid < 64) sb[tid] = (tid < NBLK) ? __ldcg(&g_bsum[tid]) : 0;
    __syncthreads();
#pragma unroll
    for (int off = 1; off < 64; off <<= 1) {
        int t = (tid < 64 && tid >= off) ? sb[tid - off] : 0;
        __syncthreads();
        if (tid < 64) sb[tid] += t;
        __syncthreads();
    }
    if (b == 0 && tid == 0) g_rowptr[NNODES] = sb[NBLK - 1];
    if (gt < NNODES) {
        int s_off = (b > 0 && b < NBLK) ? sb[b - 1] : 0;
        int o = g_rowptr[gt] + s_off;
        g_rowptr[gt] = o;
        g_cursor[gt] = o;
    }
    grid_barrier(base + 4);

    // ---- P4: scatter edges into CSR ----
    for (int e = gt; e < NEDGES; e += NB * 1024) {
        int s = load_idx(ei, e, is64);
        int d = load_idx(ei, (long long)NEDGES + e, is64);
        if (s < 0 || s >= NNODES || d < 0 || d >= NNODES) continue;
        float w = -__ldcg(&g_dinv[s]) * __ldcg(&g_dinv[d]);
        int pos = atomicAdd(&g_cursor[d], 1);
        g_csr_src[pos] = s;
        g_csr_w[pos]   = w;
    }
}

// ---------------- sparse propagation: fp16 gather, fp32 accumulate ----------------
// HSRC: 0=g_x16, 1=g_Tx1h, 2=g_gx1h.  PID: fp32 prev buffer (or -1).  OID: fp32 output.
// HOUT: also write fp16 copy of the output to g_Tx1h.
template <int HSRC, int PID, int OID, bool HOUT>
__global__ void prop_kernel(const float* __restrict__ ext, float alpha) {
    const __half* xh = (HSRC == 0) ? g_x16 : ((HSRC == 1) ? g_Tx1h : g_gx1h);
    float* out = bufptr<OID>(ext);
    int warp = (blockIdx.x * blockDim.x + threadIdx.x) >> 5;
    if (warp >= NNODES) return;
    int lane = threadIdx.x & 31;
    int beg = g_rowptr[warp];
    int end = g_rowptr[warp + 1];
    float4 acc = make_float4(0.f, 0.f, 0.f, 0.f);
    int j = beg;
    for (; j + 4 <= end; j += 4) {
        int s0 = g_csr_src[j],     s1 = g_csr_src[j + 1];
        int s2 = g_csr_src[j + 2], s3 = g_csr_src[j + 3];
        float w0 = g_csr_w[j],     w1 = g_csr_w[j + 1];
        float w2 = g_csr_w[j + 2], w3 = g_csr_w[j + 3];
        const __half2* r0 = (const __half2*)(xh + (size_t)s0 * NFEAT) + lane * 2;
        const __half2* r1 = (const __half2*)(xh + (size_t)s1 * NFEAT) + lane * 2;
        const __half2* r2 = (const __half2*)(xh + (size_t)s2 * NFEAT) + lane * 2;
        const __half2* r3 = (const __half2*)(xh + (size_t)s3 * NFEAT) + lane * 2;
        float2 a0 = __half22float2(r0[0]), b0 = __half22float2(r0[1]);
        float2 a1 = __half22float2(r1[0]), b1 = __half22float2(r1[1]);
        float2 a2 = __half22float2(r2[0]), b2 = __half22float2(r2[1]);
        float2 a3 = __half22float2(r3[0]), b3 = __half22float2(r3[1]);
        acc.x += w0 * a0.x + w1 * a1.x + w2 * a2.x + w3 * a3.x;
        acc.y += w0 * a0.y + w1 * a1.y + w2 * a2.y + w3 * a3.y;
        acc.z += w0 * b0.x + w1 * b1.x + w2 * b2.x + w3 * b3.x;
        acc.w += w0 * b0.y + w1 * b1.y + w2 * b2.y + w3 * b3.y;
    }
    for (; j < end; j++) {
        int s   = g_csr_src[j];
        float w = g_csr_w[j];
        const __half2* r = (const __half2*)(xh + (size_t)s * NFEAT) + lane * 2;
        float2 a = __half22float2(r[0]), b = __half22float2(r[1]);
        acc.x += w * a.x; acc.y += w * a.y; acc.z += w * b.x; acc.w += w * b.y;
    }
    size_t o = (size_t)warp * NFEAT + lane * 4;
    if (PID >= 0) {
        const float* xprev = bufptr<(PID >= 0 ? PID : 0)>(ext);
        const float4 p = *(const float4*)(xprev + o);
        acc.x = alpha * acc.x - p.x;
        acc.y = alpha * acc.y - p.y;
        acc.z = alpha * acc.z - p.z;
        acc.w = alpha * acc.w - p.w;
    }
    acc.x = f2tf32(acc.x); acc.y = f2tf32(acc.y);
    acc.z = f2tf32(acc.z); acc.w = f2tf32(acc.w);
    *(float4*)(out + o) = acc;
    if (HOUT) {
        __half2* ho = (__half2*)(g_Tx1h + o);
        ho[0] = __floats2half2_rn(acc.x, acc.y);
        ho[1] = __floats2half2_rn(acc.z, acc.w);
    }
}

// ---------------- tf32 warp-MMA fused 3-term GEMM, cp.async double-buffered (R12) ----------------
// BM=128, BN=128, BK=32; 8 warps (2x4), warp tile 64x32; 256 threads.
#define GST 36
template <int FOUT, int X0ID, int X1ID, int X2ID, int OID, bool RX0>
__global__ void __launch_bounds__(256) gemm3_mma_kernel(
    const float* __restrict__ ext, const float* __restrict__ bias) {
    const float* X0 = bufptr<X0ID>(ext);
    const float* X1 = bufptr<X1ID>(ext);
    const float* X2 = bufptr<X2ID>(ext);
    const float* Wt = (FOUT == NFEAT) ? g_Wt1 : g_Wt2;
    float* out = bufptr<OID>(ext);

    __shared__ __align__(16) float As[2][128 * GST];
    __shared__ __align__(16) float Bs[2][128 * GST];

    int tid  = threadIdx.x;
    int wid  = tid >> 5;
    int lane = tid & 31;
    int wm = (wid & 1) * 64;
    int wn = (wid >> 1) * 32;
    int row0 = blockIdx.x * 128;
    int col0 = blockIdx.y * 128;
    int gp = lane >> 2;
    int tg = lane & 3;

    const uint32_t asb = smem_u32(As);
    const uint32_t bsb = smem_u32(Bs);

    float acc[4][4][4];
#pragma unroll
    for (int i = 0; i < 4; i++)
#pragma unroll
        for (int j = 0; j < 4; j++)
#pragma unroll
            for (int r = 0; r < 4; r++) acc[i][j][r] = 0.f;

    auto LOAD = [&](int ch, int buf) {
        int t  = ch >> 2;
        int k0 = (ch & 3) * 32;
        const float* Xp = (t == 0) ? X0 : ((t == 1) ? X1 : X2);
        uint32_t ab = asb + (uint32_t)buf * 128 * GST * 4;
        uint32_t bb = bsb + (uint32_t)buf * 128 * GST * 4;
#pragma unroll
        for (int i = 0; i < 4; i++) {
            int idx = tid + i * 256;
            int r   = idx >> 3;
            int c4  = (idx & 7) * 4;
            int grow = row0 + r;
            int sz = (grow < NNODES) ? 16 : 0;
            cp16(ab + (r * GST + c4) * 4, Xp + (size_t)grow * NFEAT + k0 + c4, sz);
            cp16(bb + (r * GST + c4) * 4,
                 Wt + (size_t)(col0 + r) * CF + t * NFEAT + k0 + c4, 16);
        }
        CP_COMMIT();
    };

    LOAD(0, 0);
    for (int ch = 0; ch < 12; ch++) {
        int buf = ch & 1;
        if (ch < 11) {
            LOAD(ch + 1, buf ^ 1);
            CP_WAIT(1);
        } else {
            CP_WAIT(0);
        }
        __syncthreads();

        const float* A = As[buf];
        const float* B = Bs[buf];
        const bool rnd = RX0 && (ch < 4);
#pragma unroll
        for (int ks = 0; ks < 4; ks++) {
            int kc = ks * 8 + tg;
            uint32_t afr[4][4];
#pragma unroll
            for (int mt = 0; mt < 4; mt++) {
                int m = wm + mt * 16 + gp;
                float a0 = A[m * GST + kc];
                float a1 = A[(m + 8) * GST + kc];
                float a2 = A[m * GST + kc + 4];
                float a3 = A[(m + 8) * GST + kc + 4];
                if (rnd) { a0 = f2tf32(a0); a1 = f2tf32(a1); a2 = f2tf32(a2); a3 = f2tf32(a3); }
                afr[mt][0] = __float_as_uint(a0);
                afr[mt][1] = __float_as_uint(a1);
                afr[mt][2] = __float_as_uint(a2);
                afr[mt][3] = __float_as_uint(a3);
            }
            uint32_t bfr[4][2];
#pragma unroll
            for (int nt = 0; nt < 4; nt++) {
                int n = wn + nt * 8 + gp;
                bfr[nt][0] = __float_as_uint(B[n * GST + kc]);
                bfr[nt][1] = __float_as_uint(B[n * GST + kc + 4]);
            }
#pragma unroll
            for (int mt = 0; mt < 4; mt++)
#pragma unroll
                for (int nt = 0; nt < 4; nt++)
                    mma_tf32(acc[mt][nt], afr[mt], bfr[nt]);
        }
        __syncthreads();
    }

#pragma unroll
    for (int mt = 0; mt < 4; mt++) {
#pragma unroll
        for (int nt = 0; nt < 4; nt++) {
            int gcol = col0 + wn + nt * 8 + 2 * tg;
            float2 bv = *(const float2*)(bias + gcol);
            int r0 = row0 + wm + mt * 16 + gp;
            if (r0 < NNODES) {
                float2 o0;
                o0.x = fmaxf(acc[mt][nt][0] + bv.x, 0.f);
                o0.y = fmaxf(acc[mt][nt][1] + bv.y, 0.f);
                if (OID == 3) {
                    o0.x = f2tf32(o0.x); o0.y = f2tf32(o0.y);
                    *(__half2*)(g_gx1h + (size_t)r0 * NFEAT + gcol) = __floats2half2_rn(o0.x, o0.y);
                }
                *(float2*)(out + (size_t)r0 * FOUT + gcol) = o0;
            }
            int r1 = r0 + 8;
            if (r1 < NNODES) {
                float2 o1;
                o1.x = fmaxf(acc[mt][nt][2] + bv.x, 0.f);
                o1.y = fmaxf(acc[mt][nt][3] + bv.y, 0.f);
                if (OID == 3) {
                    o1.x = f2tf32(o1.x); o1.y = f2tf32(o1.y);
                    *(__half2*)(g_gx1h + (size_t)r1 * NFEAT + gcol) = __floats2half2_rn(o1.x, o1.y);
                }
                *(float2*)(out + (size_t)r1 * FOUT + gcol) = o1;
            }
        }
    }
}

// ---------------- fused tail: pool -> fc1 -> fc2 ----------------
__global__ void __launch_bounds__(512) tail_kernel(
    const float* __restrict__ feat, const void* __restrict__ batch,
    const float* __restrict__ fc1_w, const float* __restrict__ fc1_b,
    const float* __restrict__ fc2_w, const float* __restrict__ fc2_b,
    float* __restrict__ out) {
    __shared__ float sp[CF];
    __shared__ float sh[HID];
    __shared__ int s_lo, s_hi;
    int b = blockIdx.x;
    int tid = threadIdx.x;

    if (tid < 2) {
        int target = b + tid;
        int is64 = g_is64;
        int lo = 0, hi = NNODES;
        while (lo < hi) {
            int mid = (lo + hi) >> 1;
            int v = load_idx(batch, mid, is64);
            if (v < target) lo = mid + 1;
            else hi = mid;
        }
        if (tid == 0) s_lo = lo; else s_hi = lo;
    }
    __syncthreads();
    int lo = s_lo, hi = s_hi;
    float inv = 1.f / fmaxf((float)(hi - lo), 1.f);

    if (tid < CF) {
        float s = 0.f;
        if (tid < F2) {
            for (int r = lo; r < hi; r++) s += g_gx2[(size_t)r * F2 + tid];
        } else {
            int cc = tid - F2;
            for (int r = lo; r < hi; r++) s += feat[(size_t)r * NFEAT + cc];
        }
        sp[tid] = s * inv;
    }
    __syncthreads();

    {
        float s = fc1_b[tid];
        for (int k = 0; k < CF; k++) s += sp[k] * fc1_w[(size_t)k * HID + tid];
        sh[tid] = fmaxf(s, 0.f);
    }
    __syncthreads();

    if (tid < NOUT) {
        float s = fc2_b[tid];
        for (int k = 0; k < HID; k++) s += sh[k] * fc2_w[(size_t)k * NOUT + tid];
        out[b * NOUT + tid] = s;
    }
}

// ---------------- launch ----------------
extern "C" void kernel_launch(void* const* d_in, const int* in_sizes, int n_in,
                              void* d_out, int out_size) {
    const float* feature = nullptr;
    const void* ei = nullptr;
    const void* pbatch = nullptr;
    const float *W1 = nullptr, *b1 = nullptr, *W2 = nullptr, *b2 = nullptr;
    const float *fc1_w = nullptr, *fc1_b = nullptr, *fc2_w = nullptr, *fc2_b = nullptr;
    int seen128 = 0;
    for (int i = 0; i < n_in; i++) {
        switch (in_sizes[i]) {
            case 6400000: feature = (const float*)d_in[i]; break;
            case 1200000: ei      = d_in[i]; break;
            case 50000:   pbatch  = d_in[i]; break;
            case 49152:   W1      = (const float*)d_in[i]; break;
            case 98304:   W2      = (const float*)d_in[i]; break;
            case 196608:  fc1_w   = (const float*)d_in[i]; break;
            case 512:     fc1_b   = (const float*)d_in[i]; break;
            case 65536:   fc2_w   = (const float*)d_in[i]; break;
            case 256:     b2      = (const float*)d_in[i]; break;
            case 128:
                if (seen128++ == 0) b1 = (const float*)d_in[i];
                else                fc2_b = (const float*)d_in[i];
                break;
            default: break;
        }
    }
    float* out = (float*)d_out;

    csr_kernel<<<NB, 1024>>>(ei, W1, W2, feature);

    const int PROP_BLOCKS = (NNODES * 32 + 255) / 256;

    // ---- conv1 ----
    prop_kernel<0, -1, 1, true ><<<PROP_BLOCKS, 256>>>(feature, 1.f);  // Tx1 (+fp16)
    prop_kernel<1,  0, 2, false><<<PROP_BLOCKS, 256>>>(feature, 2.f);  // Tx2 = 2P Tx1 - x
    {
        dim3 grid((NNODES + 127) / 128, NFEAT / 128);
        gemm3_mma_kernel<NFEAT, 0, 1, 2, 3, true><<<grid, 256>>>(feature, b1);
    }

    // ---- conv2 ----
    prop_kernel<2, -1, 1, true ><<<PROP_BLOCKS, 256>>>(feature, 1.f);  // Tx1 = P gx1 (+fp16)
    prop_kernel<1,  3, 2, false><<<PROP_BLOCKS, 256>>>(feature, 2.f);  // Tx2 = 2P Tx1 - gx1
    {
        dim3 grid((NNODES + 127) / 128, F2 / 128);
        gemm3_mma_kernel<F2, 3, 1, 2, 4, false><<<grid, 256>>>(feature, b2);
    }

    // ---- fused pool + fc1 + fc2 ----
    tail_kernel<<<NGR, 512>>>(feature, pbatch, fc1_w, fc1_b, fc2_w, fc2_b, out);
}

// round 17
// speedup vs baseline: 1.2541x; 1.1050x over previous
#include <cuda_runtime.h>
#include <cuda_bf16.h>
#include <cuda_fp16.h>
#include <cstdint>

#define NNODES 50000
#define NEDGES 600000
#define NFEAT  128
#define F2     256
#define CF     384
#define HID    512
#define NOUT   128
#define NGR    128
#define NBLK   49          // ceil(50000/1024)
#define NB     128         // blocks in fused CSR kernel (co-resident: 296 slots)

__device__ __forceinline__ void mma_f16(float c[4], const uint32_t a[4], const uint32_t b[2]) {
    asm volatile(
        "mma.sync.aligned.m16n8k16.row.col.f32.f16.f16.f32 "
        "{%0,%1,%2,%3}, {%4,%5,%6,%7}, {%8,%9}, {%0,%1,%2,%3};"
        : "+f"(c[0]), "+f"(c[1]), "+f"(c[2]), "+f"(c[3])
        : "r"(a[0]), "r"(a[1]), "r"(a[2]), "r"(a[3]), "r"(b[0]), "r"(b[1]));
}

__device__ __forceinline__ uint32_t smem_u32(const void* p) {
    uint32_t a;
    asm("{ .reg .u64 t; cvta.to.shared.u64 t, %1; cvt.u32.u64 %0, t; }" : "=r"(a) : "l"(p));
    return a;
}

__device__ __forceinline__ void cp16(uint32_t dst, const void* src, int sz) {
    asm volatile("cp.async.ca.shared.global [%0], [%1], 16, %2;"
                 :: "r"(dst), "l"(src), "r"(sz) : "memory");
}
#define CP_COMMIT() asm volatile("cp.async.commit_group;" ::: "memory")
#define CP_WAIT(N)  asm volatile("cp.async.wait_group %0;" :: "n"(N) : "memory")

// ---------------- scratch ----------------
__device__ __align__(256) int   g_scnt[NNODES];
__device__ __align__(256) float g_dinv[NNODES];
__device__ __align__(256) int   g_cnt[NNODES];
__device__ __align__(256) int   g_rowptr[NNODES + 1];
__device__ __align__(256) int   g_cursor[NNODES];
__device__ __align__(256) int   g_bsum[NBLK];
__device__ __align__(256) int   g_csr_src[NEDGES];
__device__ __align__(256) float g_csr_w[NEDGES];
__device__ __align__(256) float g_gx1[(size_t)NNODES * NFEAT];    // fp32 (xprev stream)
__device__ __align__(256) float g_gx2[(size_t)NNODES * F2];       // fp32 (pool input)
__device__ __align__(256) __half g_x16 [(size_t)NNODES * NFEAT];  // fp16 feature
__device__ __align__(256) __half g_Tx1h[(size_t)NNODES * NFEAT];  // fp16 Tx1
__device__ __align__(256) __half g_Tx2h[(size_t)NNODES * NFEAT];  // fp16 Tx2
__device__ __align__(256) __half g_gx1h[(size_t)NNODES * NFEAT];  // fp16 gx1
__device__ __align__(256) __half g_Wt1h[NFEAT * CF];              // fp16 Wt1 [n][k]
__device__ __align__(256) __half g_Wt2h[F2 * CF];                 // fp16 Wt2 [n][k]
__device__ int g_is64;

// grid barrier state (fused CSR kernel)
__device__ int g_bar_count;
__device__ volatile int g_bar_sense;

__device__ __forceinline__ void grid_barrier(int target) {
    __syncthreads();
    if (threadIdx.x == 0) {
        __threadfence();
        if (atomicAdd(&g_bar_count, 1) == NB - 1) {
            atomicExch(&g_bar_count, 0);
            __threadfence();
            g_bar_sense = target;
        } else {
            while (g_bar_sense < target) {}
        }
        __threadfence();
    }
    __syncthreads();
}

__device__ __forceinline__ int load_idx(const void* p, long long i, int is64) {
    if (is64) return (int)((const long long*)p)[i];
    return ((const int*)p)[i];
}

// half-buffer selector: 0=x16, 1=Tx1h, 2=Tx2h, 3=gx1h
template <int ID>
__device__ __forceinline__ const __half* hbuf() {
    if (ID == 1) return g_Tx1h;
    if (ID == 2) return g_Tx2h;
    if (ID == 3) return g_gx1h;
    return g_x16;
}

// ---------------- fused CSR build (+ fp16 feature copy + fp16 weight transpose) ----------------
__global__ void __launch_bounds__(1024) csr_kernel(const void* __restrict__ ei,
                                                   const float* __restrict__ W1,
                                                   const float* __restrict__ W2,
                                                   const float* __restrict__ feat) {
    __shared__ int warpsum[32];
    __shared__ int sb[64];
    int tid = threadIdx.x;
    int b = blockIdx.x;
    int gt = b * 1024 + tid;
    int wid = tid >> 5, lane = tid & 31;
    int base = g_bar_sense;

    // ---- P0 ----
    if (gt < NNODES) { g_scnt[gt] = 0; g_cnt[gt] = 0; }
    if (gt == 0) {
        const int* p = (const int*)ei;
        int orv = 0;
        for (int j = 0; j < 64; j++) orv |= p[2 * j + 1];
        g_is64 = (orv == 0) ? 1 : 0;
    }
    for (int i = gt; i < CF * NFEAT; i += NB * 1024) {
        int kk = i / NFEAT, n = i % NFEAT;
        g_Wt1h[(size_t)n * CF + kk] = __float2half_rn(W1[i]);
    }
    for (int i = gt; i < CF * F2; i += NB * 1024) {
        int kk = i / F2, n = i % F2;
        g_Wt2h[(size_t)n * CF + kk] = __float2half_rn(W2[i]);
    }
    {
        const float4* f4 = (const float4*)feat;
        __half2* h2 = (__half2*)g_x16;
        for (int i = gt; i < NNODES * NFEAT / 4; i += NB * 1024) {
            float4 v = f4[i];
            h2[i * 2]     = __floats2half2_rn(v.x, v.y);
            h2[i * 2 + 1] = __floats2half2_rn(v.z, v.w);
        }
    }
    grid_barrier(base + 1);

    // ---- P1: degree counts ----
    int is64 = __ldcg(&g_is64);
    for (int e = gt; e < NEDGES; e += NB * 1024) {
        int s = load_idx(ei, e, is64);
        int d = load_idx(ei, (long long)NEDGES + e, is64);
        if (s < 0 || s >= NNODES || d < 0 || d >= NNODES) continue;
        atomicAdd(&g_scnt[s], 1);
        atomicAdd(&g_cnt[d], 1);
    }
    grid_barrier(base + 2);

    // ---- P2: dinv + per-chunk exclusive scan ----
    if (gt < NNODES) {
        float dg = (float)__ldcg(&g_scnt[gt]);
        g_dinv[gt] = (dg > 0.f) ? rsqrtf(dg) : 0.f;
    }
    {
        int v = (b < NBLK && gt < NNODES) ? __ldcg(&g_cnt[gt]) : 0;
        int x = v;
#pragma unroll
        for (int off = 1; off < 32; off <<= 1) {
            int n = __shfl_up_sync(0xFFFFFFFFu, x, off);
            if (lane >= off) x += n;
        }
        if (lane == 31) warpsum[wid] = x;
        __syncthreads();
        if (wid == 0) {
            int y = warpsum[lane];
#pragma unroll
            for (int off = 1; off < 32; off <<= 1) {
                int n = __shfl_up_sync(0xFFFFFFFFu, y, off);
                if (lane >= off) y += n;
            }
            warpsum[lane] = y;
        }
        __syncthreads();
        int incl = x + (wid > 0 ? warpsum[wid - 1] : 0);
        if (b < NBLK) {
            if (gt < NNODES) g_rowptr[gt] = incl - v;
            if (tid == 1023) g_bsum[b] = incl;
        }
    }
    grid_barrier(base + 3);

    // ---- P3: block-sum scan + finalize rowptr/cursor ----
    if (tid < 64) sb[tid] = (tid < NBLK) ? __ldcg(&g_bsum[tid]) : 0;
    __syncthreads();
#pragma unroll
    for (int off = 1; off < 64; off <<= 1) {
        int t = (tid < 64 && tid >= off) ? sb[tid - off] : 0;
        __syncthreads();
        if (tid < 64) sb[tid] += t;
        __syncthreads();
    }
    if (b == 0 && tid == 0) g_rowptr[NNODES] = sb[NBLK - 1];
    if (gt < NNODES) {
        int s_off = (b > 0 && b < NBLK) ? sb[b - 1] : 0;
        int o = g_rowptr[gt] + s_off;
        g_rowptr[gt] = o;
        g_cursor[gt] = o;
    }
    grid_barrier(base + 4);

    // ---- P4: scatter edges into CSR ----
    for (int e = gt; e < NEDGES; e += NB * 1024) {
        int s = load_idx(ei, e, is64);
        int d = load_idx(ei, (long long)NEDGES + e, is64);
        if (s < 0 || s >= NNODES || d < 0 || d >= NNODES) continue;
        float w = -__ldcg(&g_dinv[s]) * __ldcg(&g_dinv[d]);
        int pos = atomicAdd(&g_cursor[d], 1);
        g_csr_src[pos] = s;
        g_csr_w[pos]   = w;
    }
}

// ---------------- sparse propagation: fp16 gather, fp32 accumulate, fp16 output ----------------
// HSRC: gather source. PID: -1 none, 0 feature(ext), 3 g_gx1. HDST: 1=Tx1h, 2=Tx2h.
template <int HSRC, int PID, int HDST>
__global__ void prop_kernel(const float* __restrict__ ext, float alpha) {
    const __half* xh = hbuf<HSRC>();
    __half* outh = (HDST == 1) ? g_Tx1h : g_Tx2h;
    int warp = (blockIdx.x * blockDim.x + threadIdx.x) >> 5;
    if (warp >= NNODES) return;
    int lane = threadIdx.x & 31;
    int beg = g_rowptr[warp];
    int end = g_rowptr[warp + 1];
    float4 acc = make_float4(0.f, 0.f, 0.f, 0.f);
    int j = beg;
    for (; j + 4 <= end; j += 4) {
        int s0 = g_csr_src[j],     s1 = g_csr_src[j + 1];
        int s2 = g_csr_src[j + 2], s3 = g_csr_src[j + 3];
        float w0 = g_csr_w[j],     w1 = g_csr_w[j + 1];
        float w2 = g_csr_w[j + 2], w3 = g_csr_w[j + 3];
        const __half2* r0 = (const __half2*)(xh + (size_t)s0 * NFEAT) + lane * 2;
        const __half2* r1 = (const __half2*)(xh + (size_t)s1 * NFEAT) + lane * 2;
        const __half2* r2 = (const __half2*)(xh + (size_t)s2 * NFEAT) + lane * 2;
        const __half2* r3 = (const __half2*)(xh + (size_t)s3 * NFEAT) + lane * 2;
        float2 a0 = __half22float2(r0[0]), b0 = __half22float2(r0[1]);
        float2 a1 = __half22float2(r1[0]), b1 = __half22float2(r1[1]);
        float2 a2 = __half22float2(r2[0]), b2 = __half22float2(r2[1]);
        float2 a3 = __half22float2(r3[0]), b3 = __half22float2(r3[1]);
        acc.x += w0 * a0.x + w1 * a1.x + w2 * a2.x + w3 * a3.x;
        acc.y += w0 * a0.y + w1 * a1.y + w2 * a2.y + w3 * a3.y;
        acc.z += w0 * b0.x + w1 * b1.x + w2 * b2.x + w3 * b3.x;
        acc.w += w0 * b0.y + w1 * b1.y + w2 * b2.y + w3 * b3.y;
    }
    for (; j < end; j++) {
        int s   = g_csr_src[j];
        float w = g_csr_w[j];
        const __half2* r = (const __half2*)(xh + (size_t)s * NFEAT) + lane * 2;
        float2 a = __half22float2(r[0]), b = __half22float2(r[1]);
        acc.x += w * a.x; acc.y += w * a.y; acc.z += w * b.x; acc.w += w * b.y;
    }
    size_t o = (size_t)warp * NFEAT + lane * 4;
    if (PID >= 0) {
        const float* xprev = (PID == 3) ? g_gx1 : ext;
        const float4 p = *(const float4*)(xprev + o);
        acc.x = alpha * acc.x - p.x;
        acc.y = alpha * acc.y - p.y;
        acc.z = alpha * acc.z - p.z;
        acc.w = alpha * acc.w - p.w;
    }
    __half2* ho = (__half2*)(outh + o);
    ho[0] = __floats2half2_rn(acc.x, acc.y);
    ho[1] = __floats2half2_rn(acc.z, acc.w);
}

// ---------------- fp16 warp-MMA fused 3-term GEMM, cp.async double-buffered ----------------
// BM=128, BN=128, BK=32; 8 warps (2x4), warp tile 64x32; 256 threads; m16n8k16.
// A/B tiles fp16 [row][GSTH=40 halfs]; fragments load as half2 (conflict-free).
#define GSTH 40
template <int FOUT, int X0ID, int X1ID, int X2ID, bool WGX1>
__global__ void __launch_bounds__(256) gemm3_mma_kernel(
    const float* __restrict__ bias) {
    const __half* X0 = hbuf<X0ID>();
    const __half* X1 = hbuf<X1ID>();
    const __half* X2 = hbuf<X2ID>();
    const __half* Wt = (FOUT == NFEAT) ? g_Wt1h : g_Wt2h;
    float* out = WGX1 ? g_gx1 : g_gx2;

    __shared__ __align__(16) __half As[2][128 * GSTH];
    __shared__ __align__(16) __half Bs[2][128 * GSTH];

    int tid  = threadIdx.x;
    int wid  = tid >> 5;
    int lane = tid & 31;
    int wm = (wid & 1) * 64;
    int wn = (wid >> 1) * 32;
    int row0 = blockIdx.x * 128;
    int col0 = blockIdx.y * 128;
    int gp = lane >> 2;
    int tg = lane & 3;

    const uint32_t asb = smem_u32(As);
    const uint32_t bsb = smem_u32(Bs);

    float acc[4][4][4];
#pragma unroll
    for (int i = 0; i < 4; i++)
#pragma unroll
        for (int j = 0; j < 4; j++)
#pragma unroll
            for (int r = 0; r < 4; r++) acc[i][j][r] = 0.f;

    // per chunk: A tile 128x32 halfs = 8 KB = 512 x 16B units -> 2 per thread; same for B
    auto LOAD = [&](int ch, int buf) {
        int t  = ch >> 2;
        int k0 = (ch & 3) * 32;
        const __half* Xp = (t == 0) ? X0 : ((t == 1) ? X1 : X2);
        uint32_t ab = asb + (uint32_t)buf * 128 * GSTH * 2;
        uint32_t bb = bsb + (uint32_t)buf * 128 * GSTH * 2;
#pragma unroll
        for (int i = 0; i < 2; i++) {
            int idx = tid + i * 256;
            int r   = idx >> 2;          // 0..127
            int c8  = (idx & 3) * 8;     // 0,8,16,24 halfs
            int grow = row0 + r;
            int sz = (grow < NNODES) ? 16 : 0;
            cp16(ab + (r * GSTH + c8) * 2, Xp + (size_t)grow * NFEAT + k0 + c8, sz);
            cp16(bb + (r * GSTH + c8) * 2,
                 Wt + (size_t)(col0 + r) * CF + t * NFEAT + k0 + c8, 16);
        }
        CP_COMMIT();
    };

    LOAD(0, 0);
    for (int ch = 0; ch < 12; ch++) {
        int buf = ch & 1;
        if (ch < 11) {
            LOAD(ch + 1, buf ^ 1);
            CP_WAIT(1);
        } else {
            CP_WAIT(0);
        }
        __syncthreads();

        const __half* A = As[buf];
        const __half* B = Bs[buf];
#pragma unroll
        for (int ks = 0; ks < 2; ks++) {       // two k16 steps per 32-k chunk
            int kc = ks * 16 + 2 * tg;
            uint32_t afr[4][4];
#pragma unroll
            for (int mt = 0; mt < 4; mt++) {
                int m = wm + mt * 16 + gp;
                afr[mt][0] = *(const uint32_t*)&A[m * GSTH + kc];           // row m,   k kc..kc+1
                afr[mt][1] = *(const uint32_t*)&A[(m + 8) * GSTH + kc];     // row m+8
                afr[mt][2] = *(const uint32_t*)&A[m * GSTH + kc + 8];       // row m,   k +8
                afr[mt][3] = *(const uint32_t*)&A[(m + 8) * GSTH + kc + 8]; // row m+8, k +8
            }
            uint32_t bfr[4][2];
#pragma unroll
            for (int nt = 0; nt < 4; nt++) {
                int n = wn + nt * 8 + gp;
                bfr[nt][0] = *(const uint32_t*)&B[n * GSTH + kc];
                bfr[nt][1] = *(const uint32_t*)&B[n * GSTH + kc + 8];
            }
#pragma unroll
            for (int mt = 0; mt < 4; mt++)
#pragma unroll
                for (int nt = 0; nt < 4; nt++)
                    mma_f16(acc[mt][nt], afr[mt], bfr[nt]);
        }
        __syncthreads();
    }

    // epilogue: bias + relu; gx1 also mirrored to fp16
#pragma unroll
    for (int mt = 0; mt < 4; mt++) {
#pragma unroll
        for (int nt = 0; nt < 4; nt++) {
            int gcol = col0 + wn + nt * 8 + 2 * tg;
            float2 bv = *(const float2*)(bias + gcol);
            int r0 = row0 + wm + mt * 16 + gp;
            if (r0 < NNODES) {
                float2 o0;
                o0.x = fmaxf(acc[mt][nt][0] + bv.x, 0.f);
                o0.y = fmaxf(acc[mt][nt][1] + bv.y, 0.f);
                if (WGX1)
                    *(__half2*)(g_gx1h + (size_t)r0 * NFEAT + gcol) = __floats2half2_rn(o0.x, o0.y);
                *(float2*)(out + (size_t)r0 * FOUT + gcol) = o0;
            }
            int r1 = r0 + 8;
            if (r1 < NNODES) {
                float2 o1;
                o1.x = fmaxf(acc[mt][nt][2] + bv.x, 0.f);
                o1.y = fmaxf(acc[mt][nt][3] + bv.y, 0.f);
                if (WGX1)
                    *(__half2*)(g_gx1h + (size_t)r1 * NFEAT + gcol) = __floats2half2_rn(o1.x, o1.y);
                *(float2*)(out + (size_t)r1 * FOUT + gcol) = o1;
            }
        }
    }
}

// ---------------- fused tail: pool -> fc1 -> fc2 ----------------
__global__ void __launch_bounds__(512) tail_kernel(
    const float* __restrict__ feat, const void* __restrict__ batch,
    const float* __restrict__ fc1_w, const float* __restrict__ fc1_b,
    const float* __restrict__ fc2_w, const float* __restrict__ fc2_b,
    float* __restrict__ out) {
    __shared__ float sp[CF];
    __shared__ float sh[HID];
    __shared__ int s_lo, s_hi;
    int b = blockIdx.x;
    int tid = threadIdx.x;

    if (tid < 2) {
        int target = b + tid;
        int is64 = g_is64;
        int lo = 0, hi = NNODES;
        while (lo < hi) {
            int mid = (lo + hi) >> 1;
            int v = load_idx(batch, mid, is64);
            if (v < target) lo = mid + 1;
            else hi = mid;
        }
        if (tid == 0) s_lo = lo; else s_hi = lo;
    }
    __syncthreads();
    int lo = s_lo, hi = s_hi;
    float inv = 1.f / fmaxf((float)(hi - lo), 1.f);

    if (tid < CF) {
        float s = 0.f;
        if (tid < F2) {
            for (int r = lo; r < hi; r++) s += g_gx2[(size_t)r * F2 + tid];
        } else {
            int cc = tid - F2;
            for (int r = lo; r < hi; r++) s += feat[(size_t)r * NFEAT + cc];
        }
        sp[tid] = s * inv;
    }
    __syncthreads();

    {
        float s = fc1_b[tid];
        for (int k = 0; k < CF; k++) s += sp[k] * fc1_w[(size_t)k * HID + tid];
        sh[tid] = fmaxf(s, 0.f);
    }
    __syncthreads();

    if (tid < NOUT) {
        float s = fc2_b[tid];
        for (int k = 0; k < HID; k++) s += sh[k] * fc2_w[(size_t)k * NOUT + tid];
        out[b * NOUT + tid] = s;
    }
}

// ---------------- launch ----------------
extern "C" void kernel_launch(void* const* d_in, const int* in_sizes, int n_in,
                              void* d_out, int out_size) {
    const float* feature = nullptr;
    const void* ei = nullptr;
    const void* pbatch = nullptr;
    const float *W1 = nullptr, *b1 = nullptr, *W2 = nullptr, *b2 = nullptr;
    const float *fc1_w = nullptr, *fc1_b = nullptr, *fc2_w = nullptr, *fc2_b = nullptr;
    int seen128 = 0;
    for (int i = 0; i < n_in; i++) {
        switch (in_sizes[i]) {
            case 6400000: feature = (const float*)d_in[i]; break;
            case 1200000: ei      = d_in[i]; break;
            case 50000:   pbatch  = d_in[i]; break;
            case 49152:   W1      = (const float*)d_in[i]; break;
            case 98304:   W2      = (const float*)d_in[i]; break;
            case 196608:  fc1_w   = (const float*)d_in[i]; break;
            case 512:     fc1_b   = (const float*)d_in[i]; break;
            case 65536:   fc2_w   = (const float*)d_in[i]; break;
            case 256:     b2      = (const float*)d_in[i]; break;
            case 128:
                if (seen128++ == 0) b1 = (const float*)d_in[i];
                else                fc2_b = (const float*)d_in[i];
                break;
            default: break;
        }
    }
    float* out = (float*)d_out;

    csr_kernel<<<NB, 1024>>>(ei, W1, W2, feature);

    const int PROP_BLOCKS = (NNODES * 32 + 255) / 256;

    // ---- conv1 ----
    prop_kernel<0, -1, 1><<<PROP_BLOCKS, 256>>>(feature, 1.f);   // Tx1h = P x
    prop_kernel<1,  0, 2><<<PROP_BLOCKS, 256>>>(feature, 2.f);   // Tx2h = 2P Tx1 - x
    {
        dim3 grid((NNODES + 127) / 128, NFEAT / 128);
        gemm3_mma_kernel<NFEAT, 0, 1, 2, true><<<grid, 256>>>(b1);
    }

    // ---- conv2 ----
    prop_kernel<3, -1, 1><<<PROP_BLOCKS, 256>>>(feature, 1.f);   // Tx1h = P gx1
    prop_kernel<1,  3, 2><<<PROP_BLOCKS, 256>>>(feature, 2.f);   // Tx2h = 2P Tx1 - gx1
    {
        dim3 grid((NNODES + 127) / 128, F2 / 128);
        gemm3_mma_kernel<F2, 3, 1, 2, false><<<grid, 256>>>(b2);
    }

    // ---- fused pool + fc1 + fc2 ----
    tail_kernel<<<NGR, 512>>>(feature, pbatch, fc1_w, fc1_b, fc2_w, fc2_b, out);
}